// round 14
// baseline (speedup 1.0000x reference)
#include <cuda_runtime.h>
#include <cuda_fp16.h>
#include <math.h>
#include <stdint.h>

#define NN 50000
#define NE 800000
#define LIN 1024
#define DH 256

// ===================== scratch (static device globals) =====================
__device__ __half g_Xh[(size_t)NN * LIN];   // fp16 copy of x
__device__ __half g_Qh[(size_t)NN * DH];
__device__ __half g_Kh[(size_t)NN * DH];
__device__ __half g_Vh[(size_t)NN * DH];
__device__ __half g_Sh[(size_t)NN * DH];
__device__ __half g_Hh[(size_t)NN * DH];    // fp16 copy of h
__device__ __half g_TAh[(size_t)NN * DH];
__device__ __half g_TBh[(size_t)NN * DH];
__device__ int    g_srcSorted[NE];
__device__ int    g_deg[NN];
__device__ int    g_off[NN + 1];
__device__ int    g_cur[NN];
__device__ float  g_scores[NN * 2];
__device__ float  g_cmax[2];
__device__ float  g_csum[2];

// fp16 weights, transposed to [N=256, K] per matrix (k-major rows).
#define WBIG (256 * 1024)
#define WSML (256 * 256)
__device__ __half g_WH[4 * WBIG + 2 * WSML];

__device__ __forceinline__ float gelu_exact(float x) {
    return 0.5f * x * (1.0f + erff(x * 0.70710678118654752440f));
}

__device__ __forceinline__ uint32_t smem_u32(const void* p) {
    uint32_t a;
    asm("{ .reg .u64 t; cvta.to.shared.u64 t, %1; cvt.u32.u64 %0, t; }" : "=r"(a) : "l"(p));
    return a;
}

#define LDM_X4(r0, r1, r2, r3, addr) \
    asm volatile("ldmatrix.sync.aligned.m8n8.x4.shared.b16 {%0,%1,%2,%3}, [%4];" \
                 : "=r"(r0), "=r"(r1), "=r"(r2), "=r"(r3) : "r"(addr))

#define CP16(dst, src) \
    asm volatile("cp.async.cg.shared.global [%0], [%1], 16;" :: "r"(dst), "l"(src))

__device__ __forceinline__ void mma_f16(float* d, const uint32_t* a, const uint32_t* b) {
    asm volatile(
        "mma.sync.aligned.m16n8k16.row.col.f32.f16.f16.f32 "
        "{%0,%1,%2,%3},{%4,%5,%6,%7},{%8,%9},{%0,%1,%2,%3};"
        : "+f"(d[0]), "+f"(d[1]), "+f"(d[2]), "+f"(d[3])
        : "r"(a[0]), "r"(a[1]), "r"(a[2]), "r"(a[3]), "r"(b[0]), "r"(b[1]));
}

// ===================== init =====================
__global__ void init_kernel(float* __restrict__ out) {
    int i = blockIdx.x * blockDim.x + threadIdx.x;
    if (i < NN) g_deg[i] = 0;
    if (i < 512) out[i] = 0.0f;
}

// ===================== CSR build =====================
__global__ void count_kernel(const int* __restrict__ ei) {
    int e = blockIdx.x * blockDim.x + threadIdx.x;
    if (e < NE) atomicAdd(&g_deg[ei[NE + e]], 1);
}

__global__ void scan_kernel() {
    __shared__ int wsum[32];
    int tid = threadIdx.x, lane = tid & 31, w = tid >> 5;
    int carry = 0;
    for (int base = 0; base < NN; base += 1024) {
        int idx = base + tid;
        int v = (idx < NN) ? g_deg[idx] : 0;
        int x = v;
        #pragma unroll
        for (int o = 1; o < 32; o <<= 1) {
            int t = __shfl_up_sync(0xffffffffu, x, o);
            if (lane >= o) x += t;
        }
        if (lane == 31) wsum[w] = x;
        __syncthreads();
        if (w == 0) {
            int s = wsum[lane];
            #pragma unroll
            for (int o = 1; o < 32; o <<= 1) {
                int t = __shfl_up_sync(0xffffffffu, s, o);
                if (lane >= o) s += t;
            }
            wsum[lane] = s;
        }
        __syncthreads();
        int excl = x - v + (w ? wsum[w - 1] : 0) + carry;
        if (idx < NN) { g_off[idx] = excl; g_cur[idx] = excl; }
        int total = wsum[31];
        __syncthreads();
        carry += total;
    }
    if (tid == 0) g_off[NN] = carry;
}

__global__ void scatter_kernel(const int* __restrict__ ei) {
    int e = blockIdx.x * blockDim.x + threadIdx.x;
    if (e < NE) {
        int d = ei[NE + e];
        int p = atomicAdd(&g_cur[d], 1);
        g_srcSorted[p] = ei[e];
    }
}

// ===================== weight convert: W[K,256] -> [N=256,K] fp16 ==============
__global__ void conv_w_kernel(const float* __restrict__ Wq, const float* __restrict__ Wk,
                              const float* __restrict__ Wv, const float* __restrict__ Ws,
                              const float* __restrict__ Wa, const float* __restrict__ Wb) {
    int mat = blockIdx.y;
    int K = (mat < 4) ? 1024 : 256;
    size_t off = (mat < 4) ? (size_t)mat * WBIG : (size_t)4 * WBIG + (size_t)(mat - 4) * WSML;
    const float* W = (mat == 0) ? Wq : (mat == 1) ? Wk : (mat == 2) ? Wv :
                     (mat == 3) ? Ws : (mat == 4) ? Wa : Wb;
    int idx = blockIdx.x * blockDim.x + threadIdx.x;
    if (idx < 256 * K) {
        int n = idx / K, k = idx % K;
        g_WH[off + idx] = __float2half_rn(W[(size_t)k * 256 + n]);
    }
}

// ===================== x convert: fp32 -> fp16, row range ======================
__global__ void conv_x_kernel(const float* __restrict__ X, int rowStart, int rowEnd) {
    size_t base = (size_t)rowStart * LIN;
    size_t lim  = (size_t)rowEnd * LIN;
    size_t i = base + ((size_t)blockIdx.x * blockDim.x + threadIdx.x) * 8;
    if (i < lim) {
        float4 a = *(const float4*)(X + i);
        float4 b = *(const float4*)(X + i + 4);
        uint4 pk;
        __half2 h0 = __floats2half2_rn(a.x, a.y);
        __half2 h1 = __floats2half2_rn(a.z, a.w);
        __half2 h2 = __floats2half2_rn(b.x, b.y);
        __half2 h3 = __floats2half2_rn(b.z, b.w);
        pk.x = *(uint32_t*)&h0; pk.y = *(uint32_t*)&h1;
        pk.z = *(uint32_t*)&h2; pk.w = *(uint32_t*)&h3;
        *(uint4*)(g_Xh + i) = pk;
    }
}

// ===================== HMMA GEMM (fp16, pure cp.async, 4-stage) ================
// Block: 128(M) x 256(N), BK=32, 256 threads = 8 warps of 64x64.
#define AH_OFF 0
#define BH_OFF 10240
#define STAGE  30720
#define NSTAGE 4
#define GEMM_SMEM (NSTAGE * STAGE)
#define BM 128

template <int KDIM>
__global__ __launch_bounds__(256, 1)
void mma_gemm(const __half* __restrict__ Ah, int rowBase, int M, int matBase,
              const float* __restrict__ bias0, const float* __restrict__ bias1,
              const float* __restrict__ bias2, const float* __restrict__ bias3) {
    extern __shared__ char sm[];
    uint32_t smb = smem_u32(sm);
    int tid = threadIdx.x;
    int wid = tid >> 5;
    int lane = tid & 31;

    int mat = blockIdx.x;
    int m0 = rowBase + blockIdx.y * BM;
    size_t wOff = (KDIM == 1024) ? (size_t)mat * WBIG
                                 : (size_t)4 * WBIG + (size_t)mat * WSML;
    const float* bias = (mat == 0) ? bias0 : (mat == 1) ? bias1 : (mat == 2) ? bias2 : bias3;
    __half* Oh = (matBase == 0)
               ? ((mat == 0) ? g_Qh : (mat == 1) ? g_Kh : (mat == 2) ? g_Vh : g_Sh)
               : ((mat == 0) ? g_TAh : g_TBh);

    uint64_t gW, gA;
    {
        const __half* pw = g_WH + wOff;
        asm("cvta.to.global.u64 %0, %1;" : "=l"(gW) : "l"(pw));
        int rowA = m0 + (tid >> 1);
        if (rowA >= M) rowA = M - 1;
        const __half* pa = Ah + (size_t)rowA * KDIM + (tid & 1) * 16;
        asm("cvta.to.global.u64 %0, %1;" : "=l"(gA) : "l"(pa));
    }
    uint32_t aDst = (uint32_t)(tid >> 1) * 80u + (uint32_t)(tid & 1) * 32u;

    int wm = (wid >> 2) * 64;
    int wn = (wid & 3) * 64;
    uint32_t a_row = (uint32_t)(wm + (lane & 7) + (lane & 8));
    uint32_t a_col = (uint32_t)((lane & 16) >> 1);
    uint32_t b_row = (uint32_t)(wn + ((lane & 16) >> 1) + (lane & 7));
    uint32_t b_col = (uint32_t)(lane & 8);

    float c[4][8][4];
    #pragma unroll
    for (int i = 0; i < 4; i++)
        #pragma unroll
        for (int j = 0; j < 8; j++)
            #pragma unroll
            for (int u = 0; u < 4; u++) c[i][j][u] = 0.0f;

    constexpr int T = KDIM / 32;

    auto issue = [&](int t) {
        uint32_t db = smb + (uint32_t)((t & 3) * STAGE);
        uint64_t koff = (uint64_t)t * 64;
        CP16(db + AH_OFF + aDst, gA + koff);
        CP16(db + AH_OFF + aDst + 16, gA + koff + 16);
        #pragma unroll
        for (int rep = 0; rep < 4; rep++) {
            int i = tid + rep * 256;
            int row = i >> 2, quad = i & 3;
            uint32_t d = db + BH_OFF + (uint32_t)row * 80u + (uint32_t)quad * 16u;
            CP16(d, gW + (uint64_t)row * (KDIM * 2) + koff + quad * 16);
        }
        asm volatile("cp.async.commit_group;" ::: "memory");
    };

    issue(0);
    issue(1);
    issue(2);

    for (int t = 0; t < T; ++t) {
        if (t + 3 < T)      { asm volatile("cp.async.wait_group 2;" ::: "memory"); }
        else if (t + 2 < T) { asm volatile("cp.async.wait_group 1;" ::: "memory"); }
        else                { asm volatile("cp.async.wait_group 0;" ::: "memory"); }
        __syncthreads();

        if (t + 3 < T) issue(t + 3);

        uint32_t sb = smb + (uint32_t)((t & 3) * STAGE);
        #pragma unroll
        for (int ks = 0; ks < 2; ks++) {
            uint32_t ahr[4][4];
            #pragma unroll
            for (int i = 0; i < 4; i++) {
                uint32_t off = (a_row + i * 16) * 80u + (ks * 16 + a_col) * 2u;
                LDM_X4(ahr[i][0], ahr[i][1], ahr[i][2], ahr[i][3], sb + AH_OFF + off);
            }
            uint32_t bhr[8][2];
            #pragma unroll
            for (int p = 0; p < 4; p++) {
                uint32_t off = (b_row + p * 16) * 80u + (ks * 16 + b_col) * 2u;
                LDM_X4(bhr[2 * p][0], bhr[2 * p][1], bhr[2 * p + 1][0], bhr[2 * p + 1][1],
                       sb + BH_OFF + off);
            }
            #pragma unroll
            for (int i = 0; i < 4; i++)
                #pragma unroll
                for (int j = 0; j < 8; j++) mma_f16(c[i][j], ahr[i], bhr[j]);
        }
    }

    #pragma unroll
    for (int i = 0; i < 4; i++) {
        int r0 = m0 + wm + i * 16 + (lane >> 2);
        int r1 = r0 + 8;
        #pragma unroll
        for (int j = 0; j < 8; j++) {
            int cc = wn + j * 8 + (lane & 3) * 2;
            float bx = bias[cc], by = bias[cc + 1];
            if (r0 < M)
                *(__half2*)(Oh + (size_t)r0 * 256 + cc) =
                    __floats2half2_rn(c[i][j][0] + bx, c[i][j][1] + by);
            if (r1 < M)
                *(__half2*)(Oh + (size_t)r1 * 256 + cc) =
                    __floats2half2_rn(c[i][j][2] + bx, c[i][j][3] + by);
        }
    }
}

// ===================== fused single-pass online edge softmax + agg + gelu ======
__global__ __launch_bounds__(256)
void attn_kernel(float* __restrict__ hOut) {
    int warp = (blockIdx.x * blockDim.x + threadIdx.x) >> 5;
    int lane = threadIdx.x & 31;
    if (warp >= NN) return;
    int d = warp;

    float q[8];
    {
        uint4 qq = *(const uint4*)(g_Qh + (size_t)d * 256 + lane * 8);
        float2 a0 = __half22float2(*(__half2*)&qq.x);
        float2 a1 = __half22float2(*(__half2*)&qq.y);
        float2 a2 = __half22float2(*(__half2*)&qq.z);
        float2 a3 = __half22float2(*(__half2*)&qq.w);
        q[0] = a0.x; q[1] = a0.y; q[2] = a1.x; q[3] = a1.y;
        q[4] = a2.x; q[5] = a2.y; q[6] = a3.x; q[7] = a3.y;
    }
    int e0 = g_off[d], e1 = g_off[d + 1];

    float m = -INFINITY, den = 0.0f;
    float acc[8] = {0, 0, 0, 0, 0, 0, 0, 0};

    for (int e = e0; e < e1; ++e) {
        int s = g_srcSorted[e];
        const __half* base = g_Kh + (size_t)s * 256 + lane * 8;
        uint4 kk = *(const uint4*)base;
        uint4 vv = *(const uint4*)(g_Vh + (size_t)s * 256 + lane * 8);

        float2 k0 = __half22float2(*(__half2*)&kk.x);
        float2 k1 = __half22float2(*(__half2*)&kk.y);
        float2 k2 = __half22float2(*(__half2*)&kk.z);
        float2 k3 = __half22float2(*(__half2*)&kk.w);
        float dot = q[0] * k0.x + q[1] * k0.y + q[2] * k1.x + q[3] * k1.y
                  + q[4] * k2.x + q[5] * k2.y + q[6] * k3.x + q[7] * k3.y;
        #pragma unroll
        for (int o = 16; o; o >>= 1) dot += __shfl_xor_sync(0xffffffffu, dot, o);
        dot *= 0.0625f;

        float2 v0 = __half22float2(*(__half2*)&vv.x);
        float2 v1 = __half22float2(*(__half2*)&vv.y);
        float2 v2 = __half22float2(*(__half2*)&vv.z);
        float2 v3 = __half22float2(*(__half2*)&vv.w);

        if (dot > m) {                    // warp-uniform (dot identical post-reduce)
            float f = expf(m - dot);      // first iter: exp(-inf)=0
            den *= f;
            #pragma unroll
            for (int u = 0; u < 8; u++) acc[u] *= f;
            m = dot;
        }
        float w = expf(dot - m);
        den += w;
        acc[0] += w * v0.x; acc[1] += w * v0.y;
        acc[2] += w * v1.x; acc[3] += w * v1.y;
        acc[4] += w * v2.x; acc[5] += w * v2.y;
        acc[6] += w * v3.x; acc[7] += w * v3.y;
    }
    float inv = 1.0f / (den + 1e-16f);

    float sv[8];
    {
        uint4 ss = *(const uint4*)(g_Sh + (size_t)d * 256 + lane * 8);
        float2 a0 = __half22float2(*(__half2*)&ss.x);
        float2 a1 = __half22float2(*(__half2*)&ss.y);
        float2 a2 = __half22float2(*(__half2*)&ss.z);
        float2 a3 = __half22float2(*(__half2*)&ss.w);
        sv[0] = a0.x; sv[1] = a0.y; sv[2] = a1.x; sv[3] = a1.y;
        sv[4] = a2.x; sv[5] = a2.y; sv[6] = a3.x; sv[7] = a3.y;
    }
    float hv[8];
    #pragma unroll
    for (int u = 0; u < 8; u++) hv[u] = gelu_exact(acc[u] * inv + sv[u]);

    float4* Hr = (float4*)(hOut + (size_t)d * 256);
    Hr[2 * lane]     = make_float4(hv[0], hv[1], hv[2], hv[3]);
    Hr[2 * lane + 1] = make_float4(hv[4], hv[5], hv[6], hv[7]);

    __half2 p0 = __floats2half2_rn(hv[0], hv[1]);
    __half2 p1 = __floats2half2_rn(hv[2], hv[3]);
    __half2 p2 = __floats2half2_rn(hv[4], hv[5]);
    __half2 p3 = __floats2half2_rn(hv[6], hv[7]);
    uint4 pk;
    pk.x = *(uint32_t*)&p0; pk.y = *(uint32_t*)&p1;
    pk.z = *(uint32_t*)&p2; pk.w = *(uint32_t*)&p3;
    *(uint4*)(g_Hh + (size_t)d * 256 + lane * 8) = pk;
}

// ===================== gate + scores (fp16 TA/TB) =====================
__global__ __launch_bounds__(256)
void act_scores_kernel(const float* __restrict__ Wc, const float* __restrict__ bc) {
    int warp = (blockIdx.x * blockDim.x + threadIdx.x) >> 5;
    int lane = threadIdx.x & 31;
    if (warp >= NN) return;
    int n = warp;

    float av[8], bv[8];
    {
        uint4 aa = *(const uint4*)(g_TAh + (size_t)n * 256 + lane * 8);
        float2 x0 = __half22float2(*(__half2*)&aa.x);
        float2 x1 = __half22float2(*(__half2*)&aa.y);
        float2 x2 = __half22float2(*(__half2*)&aa.z);
        float2 x3 = __half22float2(*(__half2*)&aa.w);
        av[0] = x0.x; av[1] = x0.y; av[2] = x1.x; av[3] = x1.y;
        av[4] = x2.x; av[5] = x2.y; av[6] = x3.x; av[7] = x3.y;
        uint4 bb = *(const uint4*)(g_TBh + (size_t)n * 256 + lane * 8);
        float2 y0 = __half22float2(*(__half2*)&bb.x);
        float2 y1 = __half22float2(*(__half2*)&bb.y);
        float2 y2 = __half22float2(*(__half2*)&bb.z);
        float2 y3 = __half22float2(*(__half2*)&bb.w);
        bv[0] = y0.x; bv[1] = y0.y; bv[2] = y1.x; bv[3] = y1.y;
        bv[4] = y2.x; bv[5] = y2.y; bv[6] = y3.x; bv[7] = y3.y;
    }
    int jbase = lane * 8;
    float s0 = 0.0f, s1 = 0.0f;
    #pragma unroll
    for (int u = 0; u < 8; u++) {
        float a = tanhf(av[u]);
        float b = 1.0f / (1.0f + expf(-bv[u]));
        float g = a * b;
        s0 += g * Wc[(jbase + u) * 2 + 0];
        s1 += g * Wc[(jbase + u) * 2 + 1];
    }
    #pragma unroll
    for (int o = 16; o; o >>= 1) {
        s0 += __shfl_xor_sync(0xffffffffu, s0, o);
        s1 += __shfl_xor_sync(0xffffffffu, s1, o);
    }
    if (lane == 0) {
        g_scores[2 * n + 0] = s0 + bc[0];
        g_scores[2 * n + 1] = s1 + bc[1];
    }
}

// ===================== column softmax stats (one block per column) =============
__global__ void softmax_stats_kernel() {
    __shared__ float sh[1024];
    int tid = threadIdx.x;
    int col = blockIdx.x;
    float m = -INFINITY;
    for (int i = tid; i < NN; i += 1024)
        m = fmaxf(m, g_scores[2 * i + col]);
    sh[tid] = m; __syncthreads();
    for (int o = 512; o; o >>= 1) { if (tid < o) sh[tid] = fmaxf(sh[tid], sh[tid + o]); __syncthreads(); }
    float cm = sh[0]; __syncthreads();

    float s = 0.0f;
    for (int i = tid; i < NN; i += 1024)
        s += expf(g_scores[2 * i + col] - cm);
    sh[tid] = s; __syncthreads();
    for (int o = 512; o; o >>= 1) { if (tid < o) sh[tid] += sh[tid + o]; __syncthreads(); }
    if (tid == 0) {
        g_cmax[col] = cm;
        g_csum[col] = sh[0];
    }
}

// ===================== attn output, A, y = attn.T @ h (half2 loads) ============
__global__ __launch_bounds__(128)
void output_kernel(const int* __restrict__ label, float* __restrict__ out) {
    int t = threadIdx.x;  // 0..127, handles columns 2t, 2t+1
    float cm0 = g_cmax[0], cm1 = g_cmax[1];
    float is0 = 1.0f / g_csum[0], is1 = 1.0f / g_csum[1];
    int lbl = *label;
    float y0a = 0.0f, y0b = 0.0f, y1a = 0.0f, y1b = 0.0f;
    for (int n = blockIdx.x; n < NN; n += gridDim.x) {
        float sc0 = g_scores[2 * n], sc1 = g_scores[2 * n + 1];
        float a0 = expf(sc0 - cm0) * is0;
        float a1 = expf(sc1 - cm1) * is1;
        if (t == 0) out[512 + n] = (lbl == 0) ? a0 : a1;
        uint32_t hp = *(const uint32_t*)(g_Hh + (size_t)n * 256 + 2 * t);
        float2 hf = __half22float2(*(__half2*)&hp);
        y0a += a0 * hf.x; y0b += a0 * hf.y;
        y1a += a1 * hf.x; y1b += a1 * hf.y;
    }
    atomicAdd(&out[2 * t], y0a);
    atomicAdd(&out[2 * t + 1], y0b);
    atomicAdd(&out[256 + 2 * t], y1a);
    atomicAdd(&out[256 + 2 * t + 1], y1b);
}

// ===================== stream/event resources (created at load) ================
static cudaStream_t g_s2 = 0;
static cudaEvent_t  g_e0 = 0, g_e1 = 0, g_c[4] = {0, 0, 0, 0};
namespace {
struct StreamInit {
    StreamInit() {
        cudaStreamCreateWithFlags(&g_s2, cudaStreamNonBlocking);
        cudaEventCreateWithFlags(&g_e0, cudaEventDisableTiming);
        cudaEventCreateWithFlags(&g_e1, cudaEventDisableTiming);
        for (int i = 0; i < 4; i++) cudaEventCreateWithFlags(&g_c[i], cudaEventDisableTiming);
    }
};
static StreamInit s_streamInit;
}

// ===================== launch =====================
extern "C" void kernel_launch(void* const* d_in, const int* in_sizes, int n_in,
                              void* d_out, int out_size) {
    const float* x  = (const float*)d_in[0];
    const float* Wq = (const float*)d_in[1];  const float* bq = (const float*)d_in[2];
    const float* Wk = (const float*)d_in[3];  const float* bk = (const float*)d_in[4];
    const float* Wv = (const float*)d_in[5];  const float* bv = (const float*)d_in[6];
    const float* Ws = (const float*)d_in[7];  const float* bs = (const float*)d_in[8];
    const float* Wa = (const float*)d_in[9];  const float* ba = (const float*)d_in[10];
    const float* Wb = (const float*)d_in[11]; const float* bb = (const float*)d_in[12];
    const float* Wc = (const float*)d_in[13]; const float* bc = (const float*)d_in[14];
    const int*   ei = (const int*)d_in[15];
    const int*   lb = (const int*)d_in[16];

    float* out  = (float*)d_out;
    float* hOut = out + 512 + NN;

    cudaFuncSetAttribute(mma_gemm<LIN>, cudaFuncAttributeMaxDynamicSharedMemorySize, GEMM_SMEM);
    cudaFuncSetAttribute(mma_gemm<DH>,  cudaFuncAttributeMaxDynamicSharedMemorySize, GEMM_SMEM);

    __half* xh; cudaGetSymbolAddress((void**)&xh, g_Xh);
    __half* hh; cudaGetSymbolAddress((void**)&hh, g_Hh);

    const int CHUNK = 12500;                 // 4 row-chunks
    const int convBlocks = (CHUNK * LIN / 8 + 255) / 256;

    // ---- fork: conv_w + conv_x chunks + CSR on side stream ----
    cudaEventRecord(g_e0, 0);
    cudaStreamWaitEvent(g_s2, g_e0, 0);

    conv_w_kernel<<<dim3((256 * 1024 + 255) / 256, 6), 256, 0, g_s2>>>(Wq, Wk, Wv, Ws, Wa, Wb);
    for (int ch = 0; ch < 4; ch++) {
        conv_x_kernel<<<convBlocks, 256, 0, g_s2>>>(x, ch * CHUNK, (ch + 1) * CHUNK);
        cudaEventRecord(g_c[ch], g_s2);
    }
    init_kernel<<<(NN + 255) / 256, 256, 0, g_s2>>>(out);
    count_kernel<<<(NE + 255) / 256, 256, 0, g_s2>>>(ei);
    scan_kernel<<<1, 1024, 0, g_s2>>>();
    scatter_kernel<<<(NE + 255) / 256, 256, 0, g_s2>>>(ei);
    cudaEventRecord(g_e1, g_s2);

    // ---- main: GEMM1 in 4 row-chunks, each pipelined behind its conv chunk ----
    for (int ch = 0; ch < 4; ch++) {
        cudaStreamWaitEvent(0, g_c[ch], 0);
        int r0 = ch * CHUNK;
        int M  = (ch + 1) * CHUNK;           // bound for this chunk
        mma_gemm<LIN><<<dim3(4, (CHUNK + BM - 1) / BM), 256, GEMM_SMEM>>>(
            xh, r0, M, 0, bq, bk, bv, bs);
    }

    // ---- join: attn needs CSR + GEMM1 ----
    cudaStreamWaitEvent(0, g_e1, 0);

    attn_kernel<<<(NN * 32 + 255) / 256, 256>>>(hOut);

    // TA|TB = h @ [Wa Wb] + biases (fp16 outputs)
    mma_gemm<DH><<<dim3(2, (NN + BM - 1) / BM), 256, GEMM_SMEM>>>(
        hh, 0, NN, 4, ba, bb, ba, ba);

    act_scores_kernel<<<(NN * 32 + 255) / 256, 256>>>(Wc, bc);
    softmax_stats_kernel<<<2, 1024>>>();
    output_kernel<<<512, 128>>>(lb, out);
}

// round 17
// speedup vs baseline: 1.0398x; 1.0398x over previous
#include <cuda_runtime.h>
#include <cuda_fp16.h>
#include <math.h>
#include <stdint.h>

#define NN 50000
#define NE 800000
#define LIN 1024
#define DH 256

// ===================== scratch (static device globals) =====================
__device__ __half g_Xh[(size_t)NN * LIN];   // fp16 copy of x
__device__ __half g_Qh[(size_t)NN * DH];
__device__ __half g_Kh[(size_t)NN * DH];
__device__ __half g_Vh[(size_t)NN * DH];
__device__ __half g_Sh[(size_t)NN * DH];
__device__ __half g_Hh[(size_t)NN * DH];    // fp16 copy of h
__device__ __half g_TAh[(size_t)NN * DH];
__device__ __half g_TBh[(size_t)NN * DH];
__device__ int    g_srcSorted[NE];
__device__ int    g_deg[NN];
__device__ int    g_off[NN + 1];
__device__ int    g_cur[NN];
__device__ float  g_scores[NN * 2];
__device__ float  g_cmax[2];
__device__ float  g_csum[2];

// fp16 weights, transposed to [N=256, K] per matrix (k-major rows).
#define WBIG (256 * 1024)
#define WSML (256 * 256)
__device__ __half g_WH[4 * WBIG + 2 * WSML];

__device__ __forceinline__ float gelu_exact(float x) {
    return 0.5f * x * (1.0f + erff(x * 0.70710678118654752440f));
}

__device__ __forceinline__ uint32_t smem_u32(const void* p) {
    uint32_t a;
    asm("{ .reg .u64 t; cvta.to.shared.u64 t, %1; cvt.u32.u64 %0, t; }" : "=r"(a) : "l"(p));
    return a;
}

#define LDM_X4(r0, r1, r2, r3, addr) \
    asm volatile("ldmatrix.sync.aligned.m8n8.x4.shared.b16 {%0,%1,%2,%3}, [%4];" \
                 : "=r"(r0), "=r"(r1), "=r"(r2), "=r"(r3) : "r"(addr))

#define CP16(dst, src) \
    asm volatile("cp.async.cg.shared.global [%0], [%1], 16;" :: "r"(dst), "l"(src))

__device__ __forceinline__ void mma_f16(float* d, const uint32_t* a, const uint32_t* b) {
    asm volatile(
        "mma.sync.aligned.m16n8k16.row.col.f32.f16.f16.f32 "
        "{%0,%1,%2,%3},{%4,%5,%6,%7},{%8,%9},{%0,%1,%2,%3};"
        : "+f"(d[0]), "+f"(d[1]), "+f"(d[2]), "+f"(d[3])
        : "r"(a[0]), "r"(a[1]), "r"(a[2]), "r"(a[3]), "r"(b[0]), "r"(b[1]));
}

// ===================== init =====================
__global__ void init_kernel(float* __restrict__ out) {
    int i = blockIdx.x * blockDim.x + threadIdx.x;
    if (i < NN) g_deg[i] = 0;
    if (i < 512) out[i] = 0.0f;
}

// ===================== CSR build =====================
__global__ void count_kernel(const int* __restrict__ ei) {
    int e = blockIdx.x * blockDim.x + threadIdx.x;
    if (e < NE) atomicAdd(&g_deg[ei[NE + e]], 1);
}

__global__ void scan_kernel() {
    __shared__ int wsum[32];
    int tid = threadIdx.x, lane = tid & 31, w = tid >> 5;
    int carry = 0;
    for (int base = 0; base < NN; base += 1024) {
        int idx = base + tid;
        int v = (idx < NN) ? g_deg[idx] : 0;
        int x = v;
        #pragma unroll
        for (int o = 1; o < 32; o <<= 1) {
            int t = __shfl_up_sync(0xffffffffu, x, o);
            if (lane >= o) x += t;
        }
        if (lane == 31) wsum[w] = x;
        __syncthreads();
        if (w == 0) {
            int s = wsum[lane];
            #pragma unroll
            for (int o = 1; o < 32; o <<= 1) {
                int t = __shfl_up_sync(0xffffffffu, s, o);
                if (lane >= o) s += t;
            }
            wsum[lane] = s;
        }
        __syncthreads();
        int excl = x - v + (w ? wsum[w - 1] : 0) + carry;
        if (idx < NN) { g_off[idx] = excl; g_cur[idx] = excl; }
        int total = wsum[31];
        __syncthreads();
        carry += total;
    }
    if (tid == 0) g_off[NN] = carry;
}

__global__ void scatter_kernel(const int* __restrict__ ei) {
    int e = blockIdx.x * blockDim.x + threadIdx.x;
    if (e < NE) {
        int d = ei[NE + e];
        int p = atomicAdd(&g_cur[d], 1);
        g_srcSorted[p] = ei[e];
    }
}

// ===================== weight convert: W[K,256] -> [N=256,K] fp16 ==============
__global__ void conv_w_kernel(const float* __restrict__ Wq, const float* __restrict__ Wk,
                              const float* __restrict__ Wv, const float* __restrict__ Ws,
                              const float* __restrict__ Wa, const float* __restrict__ Wb) {
    int mat = blockIdx.y;
    int K = (mat < 4) ? 1024 : 256;
    size_t off = (mat < 4) ? (size_t)mat * WBIG : (size_t)4 * WBIG + (size_t)(mat - 4) * WSML;
    const float* W = (mat == 0) ? Wq : (mat == 1) ? Wk : (mat == 2) ? Wv :
                     (mat == 3) ? Ws : (mat == 4) ? Wa : Wb;
    int idx = blockIdx.x * blockDim.x + threadIdx.x;
    if (idx < 256 * K) {
        int n = idx / K, k = idx % K;
        g_WH[off + idx] = __float2half_rn(W[(size_t)k * 256 + n]);
    }
}

// ===================== x convert: fp32 -> fp16, row range ======================
__global__ void conv_x_kernel(const float* __restrict__ X, int rowStart, int rowEnd) {
    size_t base = (size_t)rowStart * LIN;
    size_t lim  = (size_t)rowEnd * LIN;
    size_t i = base + ((size_t)blockIdx.x * blockDim.x + threadIdx.x) * 8;
    if (i < lim) {
        float4 a = *(const float4*)(X + i);
        float4 b = *(const float4*)(X + i + 4);
        uint4 pk;
        __half2 h0 = __floats2half2_rn(a.x, a.y);
        __half2 h1 = __floats2half2_rn(a.z, a.w);
        __half2 h2 = __floats2half2_rn(b.x, b.y);
        __half2 h3 = __floats2half2_rn(b.z, b.w);
        pk.x = *(uint32_t*)&h0; pk.y = *(uint32_t*)&h1;
        pk.z = *(uint32_t*)&h2; pk.w = *(uint32_t*)&h3;
        *(uint4*)(g_Xh + i) = pk;
    }
}

// ===================== HMMA GEMM (fp16, pure cp.async, 4-stage) ================
// Block: 128(M) x 256(N), BK=32, 256 threads = 8 warps of 64x64.
#define AH_OFF 0
#define BH_OFF 10240
#define STAGE  30720
#define NSTAGE 4
#define GEMM_SMEM (NSTAGE * STAGE)
#define BM 128

template <int KDIM>
__global__ __launch_bounds__(256, 1)
void mma_gemm(const __half* __restrict__ Ah, int rowBase, int M, int matBase,
              const float* __restrict__ bias0, const float* __restrict__ bias1,
              const float* __restrict__ bias2, const float* __restrict__ bias3) {
    extern __shared__ char sm[];
    uint32_t smb = smem_u32(sm);
    int tid = threadIdx.x;
    int wid = tid >> 5;
    int lane = tid & 31;

    int mat = blockIdx.x;
    int m0 = rowBase + blockIdx.y * BM;
    size_t wOff = (KDIM == 1024) ? (size_t)mat * WBIG
                                 : (size_t)4 * WBIG + (size_t)mat * WSML;
    const float* bias = (mat == 0) ? bias0 : (mat == 1) ? bias1 : (mat == 2) ? bias2 : bias3;
    __half* Oh = (matBase == 0)
               ? ((mat == 0) ? g_Qh : (mat == 1) ? g_Kh : (mat == 2) ? g_Vh : g_Sh)
               : ((mat == 0) ? g_TAh : g_TBh);

    uint64_t gW, gA;
    {
        const __half* pw = g_WH + wOff;
        asm("cvta.to.global.u64 %0, %1;" : "=l"(gW) : "l"(pw));
        int rowA = m0 + (tid >> 1);
        if (rowA >= M) rowA = M - 1;
        const __half* pa = Ah + (size_t)rowA * KDIM + (tid & 1) * 16;
        asm("cvta.to.global.u64 %0, %1;" : "=l"(gA) : "l"(pa));
    }
    uint32_t aDst = (uint32_t)(tid >> 1) * 80u + (uint32_t)(tid & 1) * 32u;

    int wm = (wid >> 2) * 64;
    int wn = (wid & 3) * 64;
    uint32_t a_row = (uint32_t)(wm + (lane & 7) + (lane & 8));
    uint32_t a_col = (uint32_t)((lane & 16) >> 1);
    uint32_t b_row = (uint32_t)(wn + ((lane & 16) >> 1) + (lane & 7));
    uint32_t b_col = (uint32_t)(lane & 8);

    float c[4][8][4];
    #pragma unroll
    for (int i = 0; i < 4; i++)
        #pragma unroll
        for (int j = 0; j < 8; j++)
            #pragma unroll
            for (int u = 0; u < 4; u++) c[i][j][u] = 0.0f;

    constexpr int T = KDIM / 32;

    auto issue = [&](int t) {
        uint32_t db = smb + (uint32_t)((t & 3) * STAGE);
        uint64_t koff = (uint64_t)t * 64;
        CP16(db + AH_OFF + aDst, gA + koff);
        CP16(db + AH_OFF + aDst + 16, gA + koff + 16);
        #pragma unroll
        for (int rep = 0; rep < 4; rep++) {
            int i = tid + rep * 256;
            int row = i >> 2, quad = i & 3;
            uint32_t d = db + BH_OFF + (uint32_t)row * 80u + (uint32_t)quad * 16u;
            CP16(d, gW + (uint64_t)row * (KDIM * 2) + koff + quad * 16);
        }
        asm volatile("cp.async.commit_group;" ::: "memory");
    };

    issue(0);
    issue(1);
    issue(2);

    for (int t = 0; t < T; ++t) {
        if (t + 3 < T)      { asm volatile("cp.async.wait_group 2;" ::: "memory"); }
        else if (t + 2 < T) { asm volatile("cp.async.wait_group 1;" ::: "memory"); }
        else                { asm volatile("cp.async.wait_group 0;" ::: "memory"); }
        __syncthreads();

        if (t + 3 < T) issue(t + 3);

        uint32_t sb = smb + (uint32_t)((t & 3) * STAGE);
        #pragma unroll
        for (int ks = 0; ks < 2; ks++) {
            uint32_t ahr[4][4];
            #pragma unroll
            for (int i = 0; i < 4; i++) {
                uint32_t off = (a_row + i * 16) * 80u + (ks * 16 + a_col) * 2u;
                LDM_X4(ahr[i][0], ahr[i][1], ahr[i][2], ahr[i][3], sb + AH_OFF + off);
            }
            uint32_t bhr[8][2];
            #pragma unroll
            for (int p = 0; p < 4; p++) {
                uint32_t off = (b_row + p * 16) * 80u + (ks * 16 + b_col) * 2u;
                LDM_X4(bhr[2 * p][0], bhr[2 * p][1], bhr[2 * p + 1][0], bhr[2 * p + 1][1],
                       sb + BH_OFF + off);
            }
            #pragma unroll
            for (int i = 0; i < 4; i++)
                #pragma unroll
                for (int j = 0; j < 8; j++) mma_f16(c[i][j], ahr[i], bhr[j]);
        }
    }

    #pragma unroll
    for (int i = 0; i < 4; i++) {
        int r0 = m0 + wm + i * 16 + (lane >> 2);
        int r1 = r0 + 8;
        #pragma unroll
        for (int j = 0; j < 8; j++) {
            int cc = wn + j * 8 + (lane & 3) * 2;
            float bx = bias[cc], by = bias[cc + 1];
            if (r0 < M)
                *(__half2*)(Oh + (size_t)r0 * 256 + cc) =
                    __floats2half2_rn(c[i][j][0] + bx, c[i][j][1] + by);
            if (r1 < M)
                *(__half2*)(Oh + (size_t)r1 * 256 + cc) =
                    __floats2half2_rn(c[i][j][2] + bx, c[i][j][3] + by);
        }
    }
}

// ===================== fused single-pass online edge softmax + agg + gelu ======
__global__ __launch_bounds__(256)
void attn_kernel(float* __restrict__ hOut, int dstStart, int dstEnd) {
    int warp = (blockIdx.x * blockDim.x + threadIdx.x) >> 5;
    int lane = threadIdx.x & 31;
    int d = dstStart + warp;
    if (d >= dstEnd) return;

    float q[8];
    {
        uint4 qq = *(const uint4*)(g_Qh + (size_t)d * 256 + lane * 8);
        float2 a0 = __half22float2(*(__half2*)&qq.x);
        float2 a1 = __half22float2(*(__half2*)&qq.y);
        float2 a2 = __half22float2(*(__half2*)&qq.z);
        float2 a3 = __half22float2(*(__half2*)&qq.w);
        q[0] = a0.x; q[1] = a0.y; q[2] = a1.x; q[3] = a1.y;
        q[4] = a2.x; q[5] = a2.y; q[6] = a3.x; q[7] = a3.y;
    }
    int e0 = g_off[d], e1 = g_off[d + 1];

    float m = -INFINITY, den = 0.0f;
    float acc[8] = {0, 0, 0, 0, 0, 0, 0, 0};

    for (int e = e0; e < e1; ++e) {
        int s = g_srcSorted[e];
        uint4 kk = *(const uint4*)(g_Kh + (size_t)s * 256 + lane * 8);
        uint4 vv = *(const uint4*)(g_Vh + (size_t)s * 256 + lane * 8);

        float2 k0 = __half22float2(*(__half2*)&kk.x);
        float2 k1 = __half22float2(*(__half2*)&kk.y);
        float2 k2 = __half22float2(*(__half2*)&kk.z);
        float2 k3 = __half22float2(*(__half2*)&kk.w);
        float dot = q[0] * k0.x + q[1] * k0.y + q[2] * k1.x + q[3] * k1.y
                  + q[4] * k2.x + q[5] * k2.y + q[6] * k3.x + q[7] * k3.y;
        #pragma unroll
        for (int o = 16; o; o >>= 1) dot += __shfl_xor_sync(0xffffffffu, dot, o);
        dot *= 0.0625f;

        float2 v0 = __half22float2(*(__half2*)&vv.x);
        float2 v1 = __half22float2(*(__half2*)&vv.y);
        float2 v2 = __half22float2(*(__half2*)&vv.z);
        float2 v3 = __half22float2(*(__half2*)&vv.w);

        if (dot > m) {                    // warp-uniform (dot identical post-reduce)
            float f = expf(m - dot);      // first iter: exp(-inf)=0
            den *= f;
            #pragma unroll
            for (int u = 0; u < 8; u++) acc[u] *= f;
            m = dot;
        }
        float w = expf(dot - m);
        den += w;
        acc[0] += w * v0.x; acc[1] += w * v0.y;
        acc[2] += w * v1.x; acc[3] += w * v1.y;
        acc[4] += w * v2.x; acc[5] += w * v2.y;
        acc[6] += w * v3.x; acc[7] += w * v3.y;
    }
    float inv = 1.0f / (den + 1e-16f);

    float sv[8];
    {
        uint4 ss = *(const uint4*)(g_Sh + (size_t)d * 256 + lane * 8);
        float2 a0 = __half22float2(*(__half2*)&ss.x);
        float2 a1 = __half22float2(*(__half2*)&ss.y);
        float2 a2 = __half22float2(*(__half2*)&ss.z);
        float2 a3 = __half22float2(*(__half2*)&ss.w);
        sv[0] = a0.x; sv[1] = a0.y; sv[2] = a1.x; sv[3] = a1.y;
        sv[4] = a2.x; sv[5] = a2.y; sv[6] = a3.x; sv[7] = a3.y;
    }
    float hv[8];
    #pragma unroll
    for (int u = 0; u < 8; u++) hv[u] = gelu_exact(acc[u] * inv + sv[u]);

    float4* Hr = (float4*)(hOut + (size_t)d * 256);
    Hr[2 * lane]     = make_float4(hv[0], hv[1], hv[2], hv[3]);
    Hr[2 * lane + 1] = make_float4(hv[4], hv[5], hv[6], hv[7]);

    __half2 p0 = __floats2half2_rn(hv[0], hv[1]);
    __half2 p1 = __floats2half2_rn(hv[2], hv[3]);
    __half2 p2 = __floats2half2_rn(hv[4], hv[5]);
    __half2 p3 = __floats2half2_rn(hv[6], hv[7]);
    uint4 pk;
    pk.x = *(uint32_t*)&p0; pk.y = *(uint32_t*)&p1;
    pk.z = *(uint32_t*)&p2; pk.w = *(uint32_t*)&p3;
    *(uint4*)(g_Hh + (size_t)d * 256 + lane * 8) = pk;
}

// ===================== gate + scores (fp16 TA/TB, node range) ==================
__global__ __launch_bounds__(256)
void act_scores_kernel(const float* __restrict__ Wc, const float* __restrict__ bc,
                       int nStart, int nEnd) {
    int warp = (blockIdx.x * blockDim.x + threadIdx.x) >> 5;
    int lane = threadIdx.x & 31;
    int n = nStart + warp;
    if (n >= nEnd) return;

    float av[8], bv[8];
    {
        uint4 aa = *(const uint4*)(g_TAh + (size_t)n * 256 + lane * 8);
        float2 x0 = __half22float2(*(__half2*)&aa.x);
        float2 x1 = __half22float2(*(__half2*)&aa.y);
        float2 x2 = __half22float2(*(__half2*)&aa.z);
        float2 x3 = __half22float2(*(__half2*)&aa.w);
        av[0] = x0.x; av[1] = x0.y; av[2] = x1.x; av[3] = x1.y;
        av[4] = x2.x; av[5] = x2.y; av[6] = x3.x; av[7] = x3.y;
        uint4 bb = *(const uint4*)(g_TBh + (size_t)n * 256 + lane * 8);
        float2 y0 = __half22float2(*(__half2*)&bb.x);
        float2 y1 = __half22float2(*(__half2*)&bb.y);
        float2 y2 = __half22float2(*(__half2*)&bb.z);
        float2 y3 = __half22float2(*(__half2*)&bb.w);
        bv[0] = y0.x; bv[1] = y0.y; bv[2] = y1.x; bv[3] = y1.y;
        bv[4] = y2.x; bv[5] = y2.y; bv[6] = y3.x; bv[7] = y3.y;
    }
    int jbase = lane * 8;
    float s0 = 0.0f, s1 = 0.0f;
    #pragma unroll
    for (int u = 0; u < 8; u++) {
        float a = tanhf(av[u]);
        float b = 1.0f / (1.0f + expf(-bv[u]));
        float g = a * b;
        s0 += g * Wc[(jbase + u) * 2 + 0];
        s1 += g * Wc[(jbase + u) * 2 + 1];
    }
    #pragma unroll
    for (int o = 16; o; o >>= 1) {
        s0 += __shfl_xor_sync(0xffffffffu, s0, o);
        s1 += __shfl_xor_sync(0xffffffffu, s1, o);
    }
    if (lane == 0) {
        g_scores[2 * n + 0] = s0 + bc[0];
        g_scores[2 * n + 1] = s1 + bc[1];
    }
}

// ===================== column softmax stats (one block per column) =============
__global__ void softmax_stats_kernel() {
    __shared__ float sh[1024];
    int tid = threadIdx.x;
    int col = blockIdx.x;
    float m = -INFINITY;
    for (int i = tid; i < NN; i += 1024)
        m = fmaxf(m, g_scores[2 * i + col]);
    sh[tid] = m; __syncthreads();
    for (int o = 512; o; o >>= 1) { if (tid < o) sh[tid] = fmaxf(sh[tid], sh[tid + o]); __syncthreads(); }
    float cm = sh[0]; __syncthreads();

    float s = 0.0f;
    for (int i = tid; i < NN; i += 1024)
        s += expf(g_scores[2 * i + col] - cm);
    sh[tid] = s; __syncthreads();
    for (int o = 512; o; o >>= 1) { if (tid < o) sh[tid] += sh[tid + o]; __syncthreads(); }
    if (tid == 0) {
        g_cmax[col] = cm;
        g_csum[col] = sh[0];
    }
}

// ===================== attn output, A, y = attn.T @ h (half2 loads) ============
__global__ __launch_bounds__(128)
void output_kernel(const int* __restrict__ label, float* __restrict__ out) {
    int t = threadIdx.x;  // 0..127, handles columns 2t, 2t+1
    float cm0 = g_cmax[0], cm1 = g_cmax[1];
    float is0 = 1.0f / g_csum[0], is1 = 1.0f / g_csum[1];
    int lbl = *label;
    float y0a = 0.0f, y0b = 0.0f, y1a = 0.0f, y1b = 0.0f;
    for (int n = blockIdx.x; n < NN; n += gridDim.x) {
        float sc0 = g_scores[2 * n], sc1 = g_scores[2 * n + 1];
        float a0 = expf(sc0 - cm0) * is0;
        float a1 = expf(sc1 - cm1) * is1;
        if (t == 0) out[512 + n] = (lbl == 0) ? a0 : a1;
        uint32_t hp = *(const uint32_t*)(g_Hh + (size_t)n * 256 + 2 * t);
        float2 hf = __half22float2(*(__half2*)&hp);
        y0a += a0 * hf.x; y0b += a0 * hf.y;
        y1a += a1 * hf.x; y1b += a1 * hf.y;
    }
    atomicAdd(&out[2 * t], y0a);
    atomicAdd(&out[2 * t + 1], y0b);
    atomicAdd(&out[256 + 2 * t], y1a);
    atomicAdd(&out[256 + 2 * t + 1], y1b);
}

// ===================== stream/event resources (created at load) ================
static cudaStream_t g_sSide = 0, g_sg[4] = {0, 0, 0, 0};
static cudaEvent_t  g_e0 = 0, g_eW = 0, g_eCSR = 0;
static cudaEvent_t  g_cv[4] = {0, 0, 0, 0};   // conv_x chunk done
static cudaEvent_t  g_g1[4] = {0, 0, 0, 0};   // GEMM1 chunk done
static cudaEvent_t  g_aH[2] = {0, 0};         // attn half done
static cudaEvent_t  g_u[2]  = {0, 0};         // scores half done
namespace {
struct StreamInit {
    StreamInit() {
        cudaStreamCreateWithFlags(&g_sSide, cudaStreamNonBlocking);
        for (int i = 0; i < 4; i++) cudaStreamCreateWithFlags(&g_sg[i], cudaStreamNonBlocking);
        cudaEventCreateWithFlags(&g_e0, cudaEventDisableTiming);
        cudaEventCreateWithFlags(&g_eW, cudaEventDisableTiming);
        cudaEventCreateWithFlags(&g_eCSR, cudaEventDisableTiming);
        for (int i = 0; i < 4; i++) {
            cudaEventCreateWithFlags(&g_cv[i], cudaEventDisableTiming);
            cudaEventCreateWithFlags(&g_g1[i], cudaEventDisableTiming);
        }
        for (int i = 0; i < 2; i++) {
            cudaEventCreateWithFlags(&g_aH[i], cudaEventDisableTiming);
            cudaEventCreateWithFlags(&g_u[i], cudaEventDisableTiming);
        }
    }
};
static StreamInit s_streamInit;
}

// ===================== launch =====================
extern "C" void kernel_launch(void* const* d_in, const int* in_sizes, int n_in,
                              void* d_out, int out_size) {
    const float* x  = (const float*)d_in[0];
    const float* Wq = (const float*)d_in[1];  const float* bq = (const float*)d_in[2];
    const float* Wk = (const float*)d_in[3];  const float* bk = (const float*)d_in[4];
    const float* Wv = (const float*)d_in[5];  const float* bv = (const float*)d_in[6];
    const float* Ws = (const float*)d_in[7];  const float* bs = (const float*)d_in[8];
    const float* Wa = (const float*)d_in[9];  const float* ba = (const float*)d_in[10];
    const float* Wb = (const float*)d_in[11]; const float* bb = (const float*)d_in[12];
    const float* Wc = (const float*)d_in[13]; const float* bc = (const float*)d_in[14];
    const int*   ei = (const int*)d_in[15];
    const int*   lb = (const int*)d_in[16];

    float* out  = (float*)d_out;
    float* hOut = out + 512 + NN;

    cudaFuncSetAttribute(mma_gemm<LIN>, cudaFuncAttributeMaxDynamicSharedMemorySize, GEMM_SMEM);
    cudaFuncSetAttribute(mma_gemm<DH>,  cudaFuncAttributeMaxDynamicSharedMemorySize, GEMM_SMEM);

    __half* xh; cudaGetSymbolAddress((void**)&xh, g_Xh);
    __half* hh; cudaGetSymbolAddress((void**)&hh, g_Hh);

    const int CHUNK = 12500;                 // 4 row-chunks of GEMM1
    const int convBlocks = (CHUNK * LIN / 8 + 255) / 256;

    // ---- fork: side stream does conv_w + CSR chain ----
    cudaEventRecord(g_e0, 0);
    cudaStreamWaitEvent(g_sSide, g_e0, 0);
    for (int i = 0; i < 4; i++) cudaStreamWaitEvent(g_sg[i], g_e0, 0);

    conv_w_kernel<<<dim3((256 * 1024 + 255) / 256, 6), 256, 0, g_sSide>>>(Wq, Wk, Wv, Ws, Wa, Wb);
    cudaEventRecord(g_eW, g_sSide);
    init_kernel<<<(NN + 255) / 256, 256, 0, g_sSide>>>(out);
    count_kernel<<<(NE + 255) / 256, 256, 0, g_sSide>>>(ei);
    scan_kernel<<<1, 1024, 0, g_sSide>>>();
    scatter_kernel<<<(NE + 255) / 256, 256, 0, g_sSide>>>(ei);
    cudaEventRecord(g_eCSR, g_sSide);

    // ---- main stream: conv_x chunks ----
    for (int ch = 0; ch < 4; ch++) {
        conv_x_kernel<<<convBlocks, 256>>>(x, ch * CHUNK, (ch + 1) * CHUNK);
        cudaEventRecord(g_cv[ch], 0);
    }

    // ---- GEMM1 chunks on 4 PARALLEL streams (tails overlap) ----
    for (int ch = 0; ch < 4; ch++) {
        cudaStreamWaitEvent(g_sg[ch], g_cv[ch], 0);
        cudaStreamWaitEvent(g_sg[ch], g_eW, 0);
        mma_gemm<LIN><<<dim3(4, (CHUNK + BM - 1) / BM), 256, GEMM_SMEM, g_sg[ch]>>>(
            xh, ch * CHUNK, (ch + 1) * CHUNK, 0, bq, bk, bv, bs);
        cudaEventRecord(g_g1[ch], g_sg[ch]);
    }

    // ---- join all GEMM1 + CSR, then attn in two halves on main ----
    for (int ch = 0; ch < 4; ch++) cudaStreamWaitEvent(0, g_g1[ch], 0);
    cudaStreamWaitEvent(0, g_eCSR, 0);

    const int HALF = 25000;
    attn_kernel<<<(HALF * 32 + 255) / 256, 256>>>(hOut, 0, HALF);
    cudaEventRecord(g_aH[0], 0);
    attn_kernel<<<(HALF * 32 + 255) / 256, 256>>>(hOut, HALF, NN);
    cudaEventRecord(g_aH[1], 0);

    // ---- GEMM2 + act_scores per half, forked (half0 overlaps attn half1) ----
    for (int hIdx = 0; hIdx < 2; hIdx++) {
        cudaStream_t st = g_sg[hIdx];
        cudaStreamWaitEvent(st, g_aH[hIdx], 0);
        mma_gemm<DH><<<dim3(2, (HALF + BM - 1) / BM), 256, GEMM_SMEM, st>>>(
            hh, hIdx * HALF, (hIdx + 1) * HALF, 4, ba, bb, ba, ba);
        act_scores_kernel<<<(HALF * 32 + 255) / 256, 256, 0, st>>>(
            Wc, bc, hIdx * HALF, (hIdx + 1) * HALF);
        cudaEventRecord(g_u[hIdx], st);
    }

    // ---- final join: stats + output on main ----
    cudaStreamWaitEvent(0, g_u[0], 0);
    cudaStreamWaitEvent(0, g_u[1], 0);
    softmax_stats_kernel<<<2, 1024>>>();
    output_kernel<<<512, 128>>>(lb, out);
}